// round 15
// baseline (speedup 1.0000x reference)
#include <cuda_runtime.h>
#include <cuda_fp16.h>
#include <math.h>

#define MAXN 100000
#define MAXE 1600000
#define MAXET (MAXE + MAXN)
#define DH 64
#define NG 128
#define NC 10
#define NEG 0.2f

// ---------------- static device scratch ----------------
// NOTE: g_deg must be zero at the start of each run. First run: static zero-init.
// Subsequent graph replays: k_pool zeroes it (after its last use in k_scatter).
__device__ int   g_is64;
__device__ int   g_esrc[MAXE];
__device__ int   g_edst[MAXE];
__device__ int   g_batch[MAXN];
__device__ int   g_deg[MAXN];
__device__ int   g_ptr[MAXN + 1];
__device__ int   g_src[MAXET];
__device__ __align__(16) __half g_h16A[MAXN * DH];   // fp16 feature ping
__device__ __align__(16) __half g_h16B[MAXN * DH];   // fp16 feature pong
__device__ __align__(16) float  g_hA[MAXN * DH];     // fp32 final-layer output (pooling)
__device__ float g_asA[MAXN], g_adA[MAXN];
__device__ float g_asB[MAXN], g_adB[MAXN];
__device__ __align__(16) float g_pool[NG * DH];
__device__ int   g_cnt[NG];

// ---------------- dtype detection: int64 (odd 32-bit words all zero) vs int32 ----------------
__global__ void k_detect(const unsigned int* __restrict__ w, int E) {
    __shared__ int nz;
    if (threadIdx.x == 0) nz = 0;
    __syncthreads();
    for (int k = threadIdx.x; k < 1024; k += blockDim.x) {
        long long pos = 2ll * ((long long)k * (E - 1) / 1024) + 1;
        if (w[pos] != 0u) atomicAdd(&nz, 1);
    }
    __syncthreads();
    if (threadIdx.x == 0) g_is64 = (nz == 0) ? 1 : 0;
}

// ---------------- fused prep: convert edges (+degcount), convert batch, zero pool ----
__global__ void k_prep(const void* __restrict__ ei, const void* __restrict__ batch,
                       int E, int n) {
    int i = blockIdx.x * blockDim.x + threadIdx.x;
    if (i < E) {
        int s, d;
        if (g_is64) {
            const long long* p = (const long long*)ei;
            s = (int)p[i];
            d = (int)p[(size_t)E + i];
        } else {
            const int* p = (const int*)ei;
            s = p[i];
            d = p[E + i];
        }
        s = min(max(s, 0), n - 1);
        d = min(max(d, 0), n - 1);
        g_esrc[i] = s;
        g_edst[i] = d;
        atomicAdd(&g_deg[d], 1);
    }
    if (i < n) {
        int v;
        if (g_is64) v = (int)((const long long*)batch)[i];
        else        v = ((const int*)batch)[i];
        g_batch[i] = min(max(v, 0), NG - 1);
    }
    if (i < NG * DH) g_pool[i] = 0.f;
    if (i < NG) g_cnt[i] = 0;
}

// ---------------- single-block exclusive scan of (deg+1) -> g_ptr ----------------
__global__ __launch_bounds__(1024) void k_scan(int n) {
    __shared__ int sh[1024];
    int tid = threadIdx.x;
    int per = (n + 1023) / 1024;
    int i0 = tid * per;
    int i1 = min(i0 + per, n);
    int s = 0;
    for (int i = i0; i < i1; i++) s += g_deg[i] + 1;   // +1 = self loop
    sh[tid] = s;
    __syncthreads();
    // Hillis-Steele inclusive scan over thread totals
    for (int o = 1; o < 1024; o <<= 1) {
        int t = (tid >= o) ? sh[tid - o] : 0;
        __syncthreads();
        sh[tid] += t;
        __syncthreads();
    }
    int off = sh[tid] - s;   // exclusive prefix for this thread's chunk
    for (int i = i0; i < i1; i++) {
        int d = g_deg[i] + 1;
        g_ptr[i] = off;
        g_deg[i] = 0;        // becomes scatter fill counter
        off += d;
    }
    if (tid == 1023) g_ptr[n] = off;   // grand total (s=0 for empty tail threads)
}

// ---------------- scatter edges (+self loops) into CSR ----------------
__global__ void k_scatter(int E, int n) {
    int i = blockIdx.x * blockDim.x + threadIdx.x;
    int tot = E + n;
    if (i >= tot) return;
    int s, d;
    if (i < E) { s = g_esrc[i]; d = g_edst[i]; }
    else       { s = d = i - E; }
    int p = atomicAdd(&g_deg[d], 1);
    g_src[g_ptr[d] + p] = s;
}

// ---------------- node transform, layer 1 (in-dim 3) -> g_h16A + asA/adA ----------------
__global__ void k_transform_in(const float* __restrict__ x, const float* __restrict__ pos,
                               const float* __restrict__ W, const float* __restrict__ asrc,
                               const float* __restrict__ adst, int n) {
    __shared__ float ss[8], sd[8];
    int g = threadIdx.x >> 6;
    int c = threadIdx.x & 63;
    int node = blockIdx.x * 4 + g;
    bool valid = node < n;
    float h = 0.f;
    if (valid) {
        float p0 = pos[node * 2];
        float p1 = pos[node * 2 + 1];
        float xv = x[node];
        h = p0 * W[c] + p1 * W[64 + c] + xv * W[128 + c];
        g_h16A[(size_t)node * DH + c] = __float2half(h);
    }
    float vs = valid ? h * asrc[c] : 0.f;
    float vd = valid ? h * adst[c] : 0.f;
#pragma unroll
    for (int o = 16; o > 0; o >>= 1) {
        vs += __shfl_xor_sync(0xffffffffu, vs, o);
        vd += __shfl_xor_sync(0xffffffffu, vd, o);
    }
    int w = threadIdx.x >> 5;
    if ((threadIdx.x & 31) == 0) { ss[w] = vs; sd[w] = vd; }
    __syncthreads();
    if (valid && (threadIdx.x & 63) == 0) {
        g_asA[node] = ss[w] + ss[w + 1];
        g_adA[node] = sd[w] + sd[w + 1];
    }
}

// ---------------- fused GAT aggregate (+ next-layer transform) ----------------
// Quarter-warp gather: 4 groups of 8 lanes; each group owns one edge per
// iteration, each lane loads uint4 (16B) of the 128B fp16 row -> 4 cache
// lines in flight per iteration from a single LDG.128.
__device__ __forceinline__ float lrelu(float t) { return t > 0.f ? t : NEG * t; }

__device__ __forceinline__ void acc_row8(float* acc, uint4 raw, float wt) {
    __half2 p0 = *reinterpret_cast<__half2*>(&raw.x);
    __half2 p1 = *reinterpret_cast<__half2*>(&raw.y);
    __half2 p2 = *reinterpret_cast<__half2*>(&raw.z);
    __half2 p3 = *reinterpret_cast<__half2*>(&raw.w);
    float2 f0 = __half22float2(p0);
    float2 f1 = __half22float2(p1);
    float2 f2 = __half22float2(p2);
    float2 f3 = __half22float2(p3);
    acc[0] += wt * f0.x;  acc[1] += wt * f0.y;
    acc[2] += wt * f1.x;  acc[3] += wt * f1.y;
    acc[4] += wt * f2.x;  acc[5] += wt * f2.y;
    acc[6] += wt * f3.x;  acc[7] += wt * f3.y;
}

__global__ __launch_bounds__(256) void k_agg_tr(
    int pp,                              // 0: read A write B; 1: read B write A
    int mode,                            // 0: fused transform; 1: final
    const float* __restrict__ bias,
    const float* __restrict__ Wn,
    const float* __restrict__ asn,
    const float* __restrict__ adn,
    int n, int nblocks)
{
    __shared__ float2 sW[DH * 32];
    __shared__ float sRow[8][DH];
    const __half* hin  = pp ? g_h16B : g_h16A;
    __half*       hout = pp ? g_h16A : g_h16B;
    const float*  as_c = pp ? g_asB : g_asA;
    const float*  ad_c = pp ? g_adB : g_adA;
    float*        as_n = pp ? g_asA : g_asB;
    float*        ad_n = pp ? g_adA : g_adB;

    int tid = threadIdx.x;
    if (mode == 0) {
        for (int i = tid; i < DH * 32; i += 256) sW[i] = ((const float2*)Wn)[i];
        __syncthreads();
    }
    int wid = tid >> 5;
    int lane = tid & 31;
    int grp = lane >> 3;    // edge group 0..3
    int c8 = lane & 7;      // uint4 index within 128B row
    float2 an2 = make_float2(0.f, 0.f), dn2 = make_float2(0.f, 0.f);
    if (mode == 0) {
        an2 = ((const float2*)asn)[lane];
        dn2 = ((const float2*)adn)[lane];
    }
    const uint4* __restrict__ h4 = (const uint4*)hin;
    float4 bb0 = ((const float4*)bias)[c8 * 2];
    float4 bb1 = ((const float4*)bias)[c8 * 2 + 1];

    for (int blk = blockIdx.x; blk < nblocks; blk += gridDim.x) {
        int node = blk * 8 + wid;
        if (node < n) {
            int start = g_ptr[node];
            int end = g_ptr[node + 1];
            int deg = end - start;   // >= 1
            float ad = ad_c[node];
            float acc[8] = {0.f, 0.f, 0.f, 0.f, 0.f, 0.f, 0.f, 0.f};
            float s = 0.f;           // lane-local unnormalized weight sum

            if (deg <= 32) {
                int sv = 0;
                float w = 0.f;
                if (lane < deg) {
                    sv = g_src[start + lane];
                    w = __expf(lrelu(as_c[sv] + ad));   // unnormalized; |e|<<88
                }
                s = w;
                // quarter-warp gather, 2-stage pipeline: 8 lines in flight
                int idx = grp;
                int st = __shfl_sync(0xffffffffu, sv, idx);
                float wt = __shfl_sync(0xffffffffu, w, idx);
                if (idx >= deg) wt = 0.f;
                uint4 raw = h4[(size_t)st * 8 + c8];
                for (int t = 4; t < deg; t += 4) {
                    int idx2 = t + grp;
                    int st2 = __shfl_sync(0xffffffffu, sv, idx2 & 31);
                    float wt2 = __shfl_sync(0xffffffffu, w, idx2 & 31);
                    if (idx2 >= deg) wt2 = 0.f;
                    uint4 raw2 = h4[(size_t)st2 * 8 + c8];
                    acc_row8(acc, raw, wt);
                    raw = raw2;
                    wt = wt2;
                }
                acc_row8(acc, raw, wt);
            } else {
                // single pass over 32-edge chunks
                for (int base = start; base < end; base += 32) {
                    int cnt = min(32, end - base);
                    int sv = 0;
                    float w = 0.f;
                    if (lane < cnt) {
                        sv = g_src[base + lane];
                        w = __expf(lrelu(as_c[sv] + ad));
                    }
                    s += w;
                    int idx = grp;
                    int st = __shfl_sync(0xffffffffu, sv, idx);
                    float wt = __shfl_sync(0xffffffffu, w, idx);
                    if (idx >= cnt) wt = 0.f;
                    uint4 raw = h4[(size_t)st * 8 + c8];
                    for (int t = 4; t < cnt; t += 4) {
                        int idx2 = t + grp;
                        int st2 = __shfl_sync(0xffffffffu, sv, idx2 & 31);
                        float wt2 = __shfl_sync(0xffffffffu, w, idx2 & 31);
                        if (idx2 >= cnt) wt2 = 0.f;
                        uint4 raw2 = h4[(size_t)st2 * 8 + c8];
                        acc_row8(acc, raw, wt);
                        raw = raw2;
                        wt = wt2;
                    }
                    acc_row8(acc, raw, wt);
                }
            }
            // reduce: weight sum across warp; acc across the 4 groups
#pragma unroll
            for (int o = 16; o > 0; o >>= 1) s += __shfl_xor_sync(0xffffffffu, s, o);
#pragma unroll
            for (int i = 0; i < 8; i++) {
                acc[i] += __shfl_xor_sync(0xffffffffu, acc[i], 8);
                acc[i] += __shfl_xor_sync(0xffffffffu, acc[i], 16);
            }
            float invs = 1.f / (s + 1e-16f);
            acc[0] = acc[0] * invs + bb0.x;
            acc[1] = acc[1] * invs + bb0.y;
            acc[2] = acc[2] * invs + bb0.z;
            acc[3] = acc[3] * invs + bb0.w;
            acc[4] = acc[4] * invs + bb1.x;
            acc[5] = acc[5] * invs + bb1.y;
            acc[6] = acc[6] * invs + bb1.z;
            acc[7] = acc[7] * invs + bb1.w;

            if (mode == 1) {
                if (grp == 0) {
                    ((float4*)g_hA)[(size_t)node * 16 + c8 * 2] =
                        make_float4(acc[0], acc[1], acc[2], acc[3]);
                    ((float4*)g_hA)[(size_t)node * 16 + c8 * 2 + 1] =
                        make_float4(acc[4], acc[5], acc[6], acc[7]);
                }
            } else {
                if (grp == 0) {
                    float4* sr = (float4*)&sRow[wid][c8 * 8];
                    sr[0] = make_float4(acc[0], acc[1], acc[2], acc[3]);
                    sr[1] = make_float4(acc[4], acc[5], acc[6], acc[7]);
                }
                __syncwarp();
                float o0 = 0.f, o1 = 0.f;
#pragma unroll
                for (int k = 0; k < DH; k++) {
                    float r = sRow[wid][k];
                    float2 w2 = sW[k * 32 + lane];
                    o0 += r * w2.x;
                    o1 += r * w2.y;
                }
                __syncwarp();
                ((__half2*)hout)[(size_t)node * 32 + lane] = __floats2half2_rn(o0, o1);
                float vs = o0 * an2.x + o1 * an2.y;
                float vd = o0 * dn2.x + o1 * dn2.y;
#pragma unroll
                for (int o = 16; o > 0; o >>= 1) {
                    vs += __shfl_xor_sync(0xffffffffu, vs, o);
                    vd += __shfl_xor_sync(0xffffffffu, vd, o);
                }
                if (lane == 0) {
                    as_n[node] = vs;
                    ad_n[node] = vd;
                }
            }
        }
    }
}

// ---------------- pooling (sorted batch, run-length pre-aggregation) + deg cleanup ----
__global__ void k_pool(int n) {
    int gi = blockIdx.x * blockDim.x + threadIdx.x;
    if (gi < n) g_deg[gi] = 0;   // reset for next graph replay

    int c = threadIdx.x & 63;
    int chunk = blockIdx.x * 4 + (threadIdx.x >> 6);
    int i0 = chunk * 64;
    if (i0 >= n) return;
    int iend = min(i0 + 64, n);
    float acc = 0.f;
    int cacc = 0;
    int cur = g_batch[i0];
    for (int i = i0; i < iend; i++) {
        int b = g_batch[i];
        if (b != cur) {
            atomicAdd(&g_pool[cur * DH + c], acc);
            if (c == 0) atomicAdd(&g_cnt[cur], cacc);
            acc = 0.f; cacc = 0; cur = b;
        }
        acc += g_hA[(size_t)i * DH + c];
        cacc++;
    }
    atomicAdd(&g_pool[cur * DH + c], acc);
    if (c == 0) atomicAdd(&g_cnt[cur], cacc);
}

// ---------------- classifier head ----------------
__global__ void k_final(const float* __restrict__ Wl, const float* __restrict__ bl,
                        float* __restrict__ out) {
    int t = blockIdx.x * blockDim.x + threadIdx.x;
    if (t >= NG * NC) return;
    int g = t / NC;
    int cls = t % NC;
    float invc = 1.f / fmaxf((float)g_cnt[g], 1.f);
    float dot = 0.f;
#pragma unroll
    for (int d = 0; d < DH; d++) dot += g_pool[g * DH + d] * Wl[d * NC + cls];
    out[t] = dot * invc + bl[cls];
}

// ---------------- host launcher ----------------
extern "C" void kernel_launch(void* const* d_in, const int* in_sizes, int n_in,
                              void* d_out, int out_size) {
    const float* x = (const float*)d_in[0];
    const float* pos = (const float*)d_in[1];
    const void* ei = d_in[2];
    const void* batch = d_in[3];
    const float* W1 = (const float*)d_in[4];
    const float* as1 = (const float*)d_in[5];
    const float* ad1 = (const float*)d_in[6];
    const float* b1 = (const float*)d_in[7];
    const float* W2 = (const float*)d_in[8];
    const float* as2 = (const float*)d_in[9];
    const float* ad2 = (const float*)d_in[10];
    const float* b2 = (const float*)d_in[11];
    const float* W3 = (const float*)d_in[12];
    const float* as3 = (const float*)d_in[13];
    const float* ad3 = (const float*)d_in[14];
    const float* b3 = (const float*)d_in[15];
    const float* Wl = (const float*)d_in[16];
    const float* bl = (const float*)d_in[17];
    float* out = (float*)d_out;

    int n = in_sizes[0];
    int E = in_sizes[2] / 2;
    int nblocks = (n + 7) / 8;

    k_detect<<<1, 256>>>((const unsigned int*)ei, E);           // launch 1
    int prepT = E > n ? E : n;
    k_prep<<<(prepT + 255) / 256, 256>>>(ei, batch, E, n);      // launch 2
    k_scan<<<1, 1024>>>(n);                                     // launch 3
    k_scatter<<<(E + n + 255) / 256, 256>>>(E, n);              // launch 4 (profiled)

    int tb = (n + 3) / 4;
    int tg = 1184;   // persistent blocks (8/SM)

    k_transform_in<<<tb, 256>>>(x, pos, W1, as1, ad1, n);
    k_agg_tr<<<tg, 256>>>(0, 0, b1, W2, as2, ad2, n, nblocks);
    k_agg_tr<<<tg, 256>>>(1, 0, b2, W3, as3, ad3, n, nblocks);
    k_agg_tr<<<nblocks, 256>>>(0, 1, b3, W3, as3, ad3, n, nblocks);

    int chunks = (n + 63) / 64;
    k_pool<<<(chunks + 3) / 4, 256>>>(n);
    k_final<<<(NG * NC + 255) / 256, 256>>>(Wl, bl, out);
}

// round 16
// speedup vs baseline: 1.4349x; 1.4349x over previous
#include <cuda_runtime.h>
#include <cuda_fp16.h>
#include <math.h>

#define MAXN 100000
#define MAXE 1600000
#define MAXET (MAXE + MAXN)
#define DH 64
#define NG 128
#define NC 10
#define NEG 0.2f

// ---------------- static device scratch ----------------
// NOTE: g_deg must be zero at the start of each run. First run: static zero-init.
// Subsequent graph replays: k_scan3 zeroes it (after its last read here).
__device__ int   g_esrc[MAXE];
__device__ int   g_edst[MAXE];
__device__ int   g_batch[MAXN];
__device__ int   g_deg[MAXN];
__device__ int   g_ptr[MAXN + 1];
__device__ int   g_ptrF[MAXN];      // scatter fill cursors (copy of row starts)
__device__ int   g_src[MAXET];
__device__ __align__(16) __half g_h16A[MAXN * DH];   // fp16 feature ping
__device__ __align__(16) __half g_h16B[MAXN * DH];   // fp16 feature pong
__device__ __align__(16) float  g_hA[MAXN * DH];     // fp32 final-layer output (pooling)
__device__ float g_asA[MAXN], g_adA[MAXN];
__device__ float g_asB[MAXN], g_adB[MAXN];
__device__ __align__(16) float g_pool[NG * DH];
__device__ int   g_cnt[NG];
__device__ int   g_part[64];

// ---------------- per-block dtype detection helper ----------------
// int64 indices < 2^31 have all odd 32-bit words zero; int32 data essentially never does.
__device__ __forceinline__ int detect_is64(const unsigned int* w, int E) {
    __shared__ int s_nz;
    if (threadIdx.x == 0) s_nz = 0;
    __syncthreads();
    if (threadIdx.x < 64) {
        long long pos = 2ll * ((long long)threadIdx.x * (E - 1) / 64) + 1;
        if (w[pos] != 0u) s_nz = 1;
    }
    __syncthreads();
    return s_nz == 0;
}

// ---------------- fused prep: dtype detect, convert edges (+degcount), batch, zero pool ----
__global__ void k_prep(const void* __restrict__ ei, const void* __restrict__ batch,
                       int E, int n) {
    int is64 = detect_is64((const unsigned int*)ei, E);
    int i = blockIdx.x * blockDim.x + threadIdx.x;
    if (i < E) {
        int s, d;
        if (is64) {
            const long long* p = (const long long*)ei;
            s = (int)p[i];
            d = (int)p[(size_t)E + i];
        } else {
            const int* p = (const int*)ei;
            s = p[i];
            d = p[E + i];
        }
        s = min(max(s, 0), n - 1);
        d = min(max(d, 0), n - 1);
        g_esrc[i] = s;
        g_edst[i] = d;
        atomicAdd(&g_deg[d], 1);
    }
    if (i < n) {
        int v;
        if (is64) v = (int)((const long long*)batch)[i];
        else      v = ((const int*)batch)[i];
        g_batch[i] = min(max(v, 0), NG - 1);
    }
    if (i < NG * DH) g_pool[i] = 0.f;
    if (i < NG) g_cnt[i] = 0;
}

// ---------------- scan part 1: per-block sums of (deg+1) ----------------
__global__ void k_scan1(int n) {
    __shared__ int sh[256];
    int base = blockIdx.x * 2048 + threadIdx.x * 8;
    int s = 0;
#pragma unroll
    for (int k = 0; k < 8; k++) {
        int idx = base + k;
        if (idx < n) s += g_deg[idx] + 1;   // +1 = self loop
    }
    sh[threadIdx.x] = s;
    __syncthreads();
    for (int o = 128; o > 0; o >>= 1) {
        if (threadIdx.x < o) sh[threadIdx.x] += sh[threadIdx.x + o];
        __syncthreads();
    }
    if (threadIdx.x == 0) g_part[blockIdx.x] = sh[0];
}

// ---------------- scan part 2: block-prefix + intra-block scan -> g_ptr, g_ptrF ----
__global__ void k_scan3(int n) {
    __shared__ int sh[256];
    int off0 = 0;
    for (int b = 0; b < (int)blockIdx.x; b++) off0 += g_part[b];
    int base = blockIdx.x * 2048 + threadIdx.x * 8;
    int loc[8], dv[8];
    int s = 0;
#pragma unroll
    for (int k = 0; k < 8; k++) {
        int idx = base + k;
        loc[k] = s;
        dv[k] = (idx < n) ? g_deg[idx] + 1 : 0;
        s += dv[k];
    }
    sh[threadIdx.x] = s;
    __syncthreads();
    for (int o = 1; o < 256; o <<= 1) {
        int t = 0;
        if ((int)threadIdx.x >= o) t = sh[threadIdx.x - o];
        __syncthreads();
        sh[threadIdx.x] += t;
        __syncthreads();
    }
    int off = off0 + sh[threadIdx.x] - s;   // exclusive
#pragma unroll
    for (int k = 0; k < 8; k++) {
        int idx = base + k;
        if (idx < n) {
            int p = off + loc[k];
            g_ptr[idx] = p;
            g_ptrF[idx] = p;                // fill cursor copy
            g_deg[idx] = 0;                 // reset for next graph replay
            if (idx == n - 1) g_ptr[n] = p + dv[k];
        }
    }
}

// ---------------- fused: scatter edges into CSR  +  layer-1 node transform ----------------
// Blocks [0, sb): scatter (single random atomic per edge via g_ptrF).
// Blocks [sb, sb+tb): input transform (independent of CSR) — overlaps scatter's L2 work.
__global__ void k_scatter_tr(int E, int n, int sb,
                             const float* __restrict__ x, const float* __restrict__ pos,
                             const float* __restrict__ W, const float* __restrict__ asrc,
                             const float* __restrict__ adst) {
    __shared__ float ss[8], sd[8];
    if ((int)blockIdx.x < sb) {
        int i = blockIdx.x * blockDim.x + threadIdx.x;
        int tot = E + n;
        if (i >= tot) return;
        int s, d;
        if (i < E) { s = g_esrc[i]; d = g_edst[i]; }
        else       { s = d = i - E; }
        int p = atomicAdd(&g_ptrF[d], 1);
        g_src[p] = s;
    } else {
        int g = threadIdx.x >> 6;
        int c = threadIdx.x & 63;
        int node = ((int)blockIdx.x - sb) * 4 + g;
        bool valid = node < n;
        float h = 0.f;
        if (valid) {
            float p0 = pos[node * 2];
            float p1 = pos[node * 2 + 1];
            float xv = x[node];
            h = p0 * W[c] + p1 * W[64 + c] + xv * W[128 + c];
            g_h16A[(size_t)node * DH + c] = __float2half(h);
        }
        float vs = valid ? h * asrc[c] : 0.f;
        float vd = valid ? h * adst[c] : 0.f;
#pragma unroll
        for (int o = 16; o > 0; o >>= 1) {
            vs += __shfl_xor_sync(0xffffffffu, vs, o);
            vd += __shfl_xor_sync(0xffffffffu, vd, o);
        }
        int w = threadIdx.x >> 5;
        if ((threadIdx.x & 31) == 0) { ss[w] = vs; sd[w] = vd; }
        __syncthreads();
        if (valid && (threadIdx.x & 63) == 0) {
            g_asA[node] = ss[w] + ss[w + 1];
            g_adA[node] = sd[w] + sd[w + 1];
        }
    }
}

// ---------------- fused GAT aggregate (+ next-layer transform) ----------------
__device__ __forceinline__ float lrelu(float t) { return t > 0.f ? t : NEG * t; }

__device__ __forceinline__ void acc_row8(float* acc, uint4 raw, float wt) {
    __half2 p0 = *reinterpret_cast<__half2*>(&raw.x);
    __half2 p1 = *reinterpret_cast<__half2*>(&raw.y);
    __half2 p2 = *reinterpret_cast<__half2*>(&raw.z);
    __half2 p3 = *reinterpret_cast<__half2*>(&raw.w);
    float2 f0 = __half22float2(p0);
    float2 f1 = __half22float2(p1);
    float2 f2 = __half22float2(p2);
    float2 f3 = __half22float2(p3);
    acc[0] += wt * f0.x;  acc[1] += wt * f0.y;
    acc[2] += wt * f1.x;  acc[3] += wt * f1.y;
    acc[4] += wt * f2.x;  acc[5] += wt * f2.y;
    acc[6] += wt * f3.x;  acc[7] += wt * f3.y;
}

__global__ __launch_bounds__(256) void k_agg_tr(
    int pp,                              // 0: read A write B; 1: read B write A
    int mode,                            // 0: fused transform; 1: final
    const float* __restrict__ bias,
    const float* __restrict__ Wn,
    const float* __restrict__ asn,
    const float* __restrict__ adn,
    int n, int nblocks)
{
    __shared__ float2 sW[DH * 32];
    __shared__ float sRow[8][DH];
    const __half* hin  = pp ? g_h16B : g_h16A;
    __half*       hout = pp ? g_h16A : g_h16B;
    const float*  as_c = pp ? g_asB : g_asA;
    const float*  ad_c = pp ? g_adB : g_adA;
    float*        as_n = pp ? g_asA : g_asB;
    float*        ad_n = pp ? g_adA : g_adB;

    int tid = threadIdx.x;
    if (mode == 0) {
        for (int i = tid; i < DH * 32; i += 256) sW[i] = ((const float2*)Wn)[i];
        __syncthreads();
    }
    int wid = tid >> 5;
    int lane = tid & 31;
    int grp = lane >> 3;    // edge group 0..3
    int c8 = lane & 7;      // uint4 index within 128B row
    float2 an2 = make_float2(0.f, 0.f), dn2 = make_float2(0.f, 0.f);
    if (mode == 0) {
        an2 = ((const float2*)asn)[lane];
        dn2 = ((const float2*)adn)[lane];
    }
    const uint4* __restrict__ h4 = (const uint4*)hin;
    float4 bb0 = ((const float4*)bias)[c8 * 2];
    float4 bb1 = ((const float4*)bias)[c8 * 2 + 1];

    for (int blk = blockIdx.x; blk < nblocks; blk += gridDim.x) {
        int node = blk * 8 + wid;
        if (node < n) {
            int start = g_ptr[node];
            int end = g_ptr[node + 1];
            int deg = end - start;   // >= 1
            float ad = ad_c[node];
            float acc[8] = {0.f, 0.f, 0.f, 0.f, 0.f, 0.f, 0.f, 0.f};
            float s = 0.f;           // lane-local unnormalized weight sum

            if (deg <= 32) {
                int sv = 0;
                float w = 0.f;
                if (lane < deg) {
                    sv = g_src[start + lane];
                    w = __expf(lrelu(as_c[sv] + ad));   // unnormalized; |e|<<88
                }
                s = w;
                int idx = grp;
                int st = __shfl_sync(0xffffffffu, sv, idx);
                float wt = __shfl_sync(0xffffffffu, w, idx);
                if (idx >= deg) wt = 0.f;
                uint4 raw = h4[(size_t)st * 8 + c8];
                for (int t = 4; t < deg; t += 4) {
                    int idx2 = t + grp;
                    int st2 = __shfl_sync(0xffffffffu, sv, idx2 & 31);
                    float wt2 = __shfl_sync(0xffffffffu, w, idx2 & 31);
                    if (idx2 >= deg) wt2 = 0.f;
                    uint4 raw2 = h4[(size_t)st2 * 8 + c8];
                    acc_row8(acc, raw, wt);
                    raw = raw2;
                    wt = wt2;
                }
                acc_row8(acc, raw, wt);
            } else {
                for (int base = start; base < end; base += 32) {
                    int cnt = min(32, end - base);
                    int sv = 0;
                    float w = 0.f;
                    if (lane < cnt) {
                        sv = g_src[base + lane];
                        w = __expf(lrelu(as_c[sv] + ad));
                    }
                    s += w;
                    int idx = grp;
                    int st = __shfl_sync(0xffffffffu, sv, idx);
                    float wt = __shfl_sync(0xffffffffu, w, idx);
                    if (idx >= cnt) wt = 0.f;
                    uint4 raw = h4[(size_t)st * 8 + c8];
                    for (int t = 4; t < cnt; t += 4) {
                        int idx2 = t + grp;
                        int st2 = __shfl_sync(0xffffffffu, sv, idx2 & 31);
                        float wt2 = __shfl_sync(0xffffffffu, w, idx2 & 31);
                        if (idx2 >= cnt) wt2 = 0.f;
                        uint4 raw2 = h4[(size_t)st2 * 8 + c8];
                        acc_row8(acc, raw, wt);
                        raw = raw2;
                        wt = wt2;
                    }
                    acc_row8(acc, raw, wt);
                }
            }
#pragma unroll
            for (int o = 16; o > 0; o >>= 1) s += __shfl_xor_sync(0xffffffffu, s, o);
#pragma unroll
            for (int i = 0; i < 8; i++) {
                acc[i] += __shfl_xor_sync(0xffffffffu, acc[i], 8);
                acc[i] += __shfl_xor_sync(0xffffffffu, acc[i], 16);
            }
            float invs = 1.f / (s + 1e-16f);
            acc[0] = acc[0] * invs + bb0.x;
            acc[1] = acc[1] * invs + bb0.y;
            acc[2] = acc[2] * invs + bb0.z;
            acc[3] = acc[3] * invs + bb0.w;
            acc[4] = acc[4] * invs + bb1.x;
            acc[5] = acc[5] * invs + bb1.y;
            acc[6] = acc[6] * invs + bb1.z;
            acc[7] = acc[7] * invs + bb1.w;

            if (mode == 1) {
                if (grp == 0) {
                    ((float4*)g_hA)[(size_t)node * 16 + c8 * 2] =
                        make_float4(acc[0], acc[1], acc[2], acc[3]);
                    ((float4*)g_hA)[(size_t)node * 16 + c8 * 2 + 1] =
                        make_float4(acc[4], acc[5], acc[6], acc[7]);
                }
            } else {
                if (grp == 0) {
                    float4* sr = (float4*)&sRow[wid][c8 * 8];
                    sr[0] = make_float4(acc[0], acc[1], acc[2], acc[3]);
                    sr[1] = make_float4(acc[4], acc[5], acc[6], acc[7]);
                }
                __syncwarp();
                float o0 = 0.f, o1 = 0.f;
#pragma unroll
                for (int k = 0; k < DH; k++) {
                    float r = sRow[wid][k];
                    float2 w2 = sW[k * 32 + lane];
                    o0 += r * w2.x;
                    o1 += r * w2.y;
                }
                __syncwarp();
                ((__half2*)hout)[(size_t)node * 32 + lane] = __floats2half2_rn(o0, o1);
                float vs = o0 * an2.x + o1 * an2.y;
                float vd = o0 * dn2.x + o1 * dn2.y;
#pragma unroll
                for (int o = 16; o > 0; o >>= 1) {
                    vs += __shfl_xor_sync(0xffffffffu, vs, o);
                    vd += __shfl_xor_sync(0xffffffffu, vd, o);
                }
                if (lane == 0) {
                    as_n[node] = vs;
                    ad_n[node] = vd;
                }
            }
        }
    }
}

// ---------------- pooling (sorted batch, run-length pre-aggregation) ----------------
__global__ void k_pool(int n) {
    int c = threadIdx.x & 63;
    int chunk = blockIdx.x * 4 + (threadIdx.x >> 6);
    int i0 = chunk * 64;
    if (i0 >= n) return;
    int iend = min(i0 + 64, n);
    float acc = 0.f;
    int cacc = 0;
    int cur = g_batch[i0];
    for (int i = i0; i < iend; i++) {
        int b = g_batch[i];
        if (b != cur) {
            atomicAdd(&g_pool[cur * DH + c], acc);
            if (c == 0) atomicAdd(&g_cnt[cur], cacc);
            acc = 0.f; cacc = 0; cur = b;
        }
        acc += g_hA[(size_t)i * DH + c];
        cacc++;
    }
    atomicAdd(&g_pool[cur * DH + c], acc);
    if (c == 0) atomicAdd(&g_cnt[cur], cacc);
}

// ---------------- classifier head ----------------
__global__ void k_final(const float* __restrict__ Wl, const float* __restrict__ bl,
                        float* __restrict__ out) {
    int t = blockIdx.x * blockDim.x + threadIdx.x;
    if (t >= NG * NC) return;
    int g = t / NC;
    int cls = t % NC;
    float invc = 1.f / fmaxf((float)g_cnt[g], 1.f);
    float dot = 0.f;
#pragma unroll
    for (int d = 0; d < DH; d++) dot += g_pool[g * DH + d] * Wl[d * NC + cls];
    out[t] = dot * invc + bl[cls];
}

// ---------------- host launcher ----------------
extern "C" void kernel_launch(void* const* d_in, const int* in_sizes, int n_in,
                              void* d_out, int out_size) {
    const float* x = (const float*)d_in[0];
    const float* pos = (const float*)d_in[1];
    const void* ei = d_in[2];
    const void* batch = d_in[3];
    const float* W1 = (const float*)d_in[4];
    const float* as1 = (const float*)d_in[5];
    const float* ad1 = (const float*)d_in[6];
    const float* b1 = (const float*)d_in[7];
    const float* W2 = (const float*)d_in[8];
    const float* as2 = (const float*)d_in[9];
    const float* ad2 = (const float*)d_in[10];
    const float* b2 = (const float*)d_in[11];
    const float* W3 = (const float*)d_in[12];
    const float* as3 = (const float*)d_in[13];
    const float* ad3 = (const float*)d_in[14];
    const float* b3 = (const float*)d_in[15];
    const float* Wl = (const float*)d_in[16];
    const float* bl = (const float*)d_in[17];
    float* out = (float*)d_out;

    int n = in_sizes[0];
    int E = in_sizes[2] / 2;
    int nb = (n + 2047) / 2048;
    int nblocks = (n + 7) / 8;

    int prepT = E > n ? E : n;
    k_prep<<<(prepT + 255) / 256, 256>>>(ei, batch, E, n);      // launch 1
    k_scan1<<<nb, 256>>>(n);                                    // launch 2
    k_scan3<<<nb, 256>>>(n);                                    // launch 3

    int sb = (E + n + 255) / 256;
    int tb = (n + 3) / 4;
    k_scatter_tr<<<sb + tb, 256>>>(E, n, sb, x, pos, W1, as1, ad1);  // launch 4 (profiled)

    int tg = 1184;   // persistent blocks (8/SM)
    k_agg_tr<<<tg, 256>>>(0, 0, b1, W2, as2, ad2, n, nblocks);
    k_agg_tr<<<tg, 256>>>(1, 0, b2, W3, as3, ad3, n, nblocks);
    k_agg_tr<<<nblocks, 256>>>(0, 1, b3, W3, as3, ad3, n, nblocks);

    int chunks = (n + 63) / 64;
    k_pool<<<(chunks + 3) / 4, 256>>>(n);
    k_final<<<(NG * NC + 255) / 256, 256>>>(Wl, bl, out);
}

// round 17
// speedup vs baseline: 1.4426x; 1.0054x over previous
#include <cuda_runtime.h>
#include <cuda_fp16.h>
#include <math.h>

#define MAXN 100000
#define MAXE 1600000
#define MAXET (MAXE + MAXN)
#define DH 64
#define NG 128
#define NC 10
#define NEG 0.2f

// ---------------- static device scratch ----------------
// NOTE: g_deg must be zero at the start of each run. First run: static zero-init.
// Subsequent graph replays: k_scan zeroes it. g_bflag reset by k_prep each run.
__device__ int   g_esrc[MAXE];
__device__ int   g_edst[MAXE];
__device__ int   g_batch[MAXN];
__device__ int   g_deg[MAXN];
__device__ int   g_ptr[MAXN + 1];
__device__ int   g_ptrF[MAXN];      // scatter fill cursors (copy of row starts)
__device__ int   g_src[MAXET];
__device__ __align__(16) __half g_h16A[MAXN * DH];   // fp16 feature ping
__device__ __align__(16) __half g_h16B[MAXN * DH];   // fp16 feature pong
__device__ __align__(16) float  g_hA[MAXN * DH];     // fp32 final-layer output (pooling)
__device__ float g_asA[MAXN], g_adA[MAXN];
__device__ float g_asB[MAXN], g_adB[MAXN];
__device__ __align__(16) float g_pool[NG * DH];
__device__ int   g_cnt[NG];
__device__ int   g_bsum[64];        // scan block aggregates
__device__ int   g_bflag[64];       // scan publish flags

// ---------------- per-block dtype detection helper ----------------
__device__ __forceinline__ int detect_is64(const unsigned int* w, int E) {
    __shared__ int s_nz;
    if (threadIdx.x == 0) s_nz = 0;
    __syncthreads();
    if (threadIdx.x < 64) {
        long long pos = 2ll * ((long long)threadIdx.x * (E - 1) / 64) + 1;
        if (w[pos] != 0u) s_nz = 1;
    }
    __syncthreads();
    return s_nz == 0;
}

// ---------------- fused prep: dtype detect, convert edges (+degcount), batch, zeros ----
__global__ void k_prep(const void* __restrict__ ei, const void* __restrict__ batch,
                       int E, int n) {
    int is64 = detect_is64((const unsigned int*)ei, E);
    int i = blockIdx.x * blockDim.x + threadIdx.x;
    if (i < E) {
        int s, d;
        if (is64) {
            const long long* p = (const long long*)ei;
            s = (int)p[i];
            d = (int)p[(size_t)E + i];
        } else {
            const int* p = (const int*)ei;
            s = p[i];
            d = p[E + i];
        }
        s = min(max(s, 0), n - 1);
        d = min(max(d, 0), n - 1);
        g_esrc[i] = s;
        g_edst[i] = d;
        atomicAdd(&g_deg[d], 1);
    }
    if (i < n) {
        int v;
        if (is64) v = (int)((const long long*)batch)[i];
        else      v = ((const int*)batch)[i];
        g_batch[i] = min(max(v, 0), NG - 1);
    }
    if (i < NG * DH) g_pool[i] = 0.f;
    if (i < NG) g_cnt[i] = 0;
    if (i < 64) g_bflag[i] = 0;
}

// ---------------- single-pass decoupled-lookback scan of (deg+1) -> g_ptr, g_ptrF ----
// Grid of <=64 blocks (all resident on 148 SMs) -> spin-wait is deadlock-free.
__global__ __launch_bounds__(256) void k_scan(int n) {
    __shared__ int sh[256];
    __shared__ int s_off;
    int tid = threadIdx.x;
    int b = blockIdx.x;
    int base = b * 2048 + tid * 8;
    int loc[8], dv[8];
    int s = 0;
#pragma unroll
    for (int k = 0; k < 8; k++) {
        int idx = base + k;
        loc[k] = s;
        dv[k] = (idx < n) ? g_deg[idx] + 1 : 0;   // +1 = self loop
        s += dv[k];
    }
    sh[tid] = s;
    if (tid == 0) s_off = 0;
    __syncthreads();
    // inclusive Hillis-Steele scan over thread totals
    for (int o = 1; o < 256; o <<= 1) {
        int t = (tid >= o) ? sh[tid - o] : 0;
        __syncthreads();
        sh[tid] += t;
        __syncthreads();
    }
    // publish this block's aggregate
    if (tid == 255) {
        g_bsum[b] = sh[255];
        __threadfence();
        atomicExch(&g_bflag[b], 1);
    }
    // lookback: sum aggregates of all preceding blocks (parallel spin)
    if (tid < b) {
        while (atomicAdd(&g_bflag[tid], 0) == 0) {}
        atomicAdd(&s_off, atomicAdd(&g_bsum[tid], 0));
    }
    __syncthreads();
    int off = s_off + sh[tid] - s;   // exclusive prefix for this thread
#pragma unroll
    for (int k = 0; k < 8; k++) {
        int idx = base + k;
        if (idx < n) {
            int p = off + loc[k];
            g_ptr[idx] = p;
            g_ptrF[idx] = p;                // fill cursor copy
            g_deg[idx] = 0;                 // reset for next graph replay
            if (idx == n - 1) g_ptr[n] = p + dv[k];
        }
    }
}

// ---------------- fused: scatter edges into CSR  +  layer-1 node transform ----------------
__global__ void k_scatter_tr(int E, int n, int sb,
                             const float* __restrict__ x, const float* __restrict__ pos,
                             const float* __restrict__ W, const float* __restrict__ asrc,
                             const float* __restrict__ adst) {
    __shared__ float ss[8], sd[8];
    if ((int)blockIdx.x < sb) {
        int i = blockIdx.x * blockDim.x + threadIdx.x;
        int tot = E + n;
        if (i >= tot) return;
        int s, d;
        if (i < E) { s = g_esrc[i]; d = g_edst[i]; }
        else       { s = d = i - E; }
        int p = atomicAdd(&g_ptrF[d], 1);
        g_src[p] = s;
    } else {
        int g = threadIdx.x >> 6;
        int c = threadIdx.x & 63;
        int node = ((int)blockIdx.x - sb) * 4 + g;
        bool valid = node < n;
        float h = 0.f;
        if (valid) {
            float p0 = pos[node * 2];
            float p1 = pos[node * 2 + 1];
            float xv = x[node];
            h = p0 * W[c] + p1 * W[64 + c] + xv * W[128 + c];
            g_h16A[(size_t)node * DH + c] = __float2half(h);
        }
        float vs = valid ? h * asrc[c] : 0.f;
        float vd = valid ? h * adst[c] : 0.f;
#pragma unroll
        for (int o = 16; o > 0; o >>= 1) {
            vs += __shfl_xor_sync(0xffffffffu, vs, o);
            vd += __shfl_xor_sync(0xffffffffu, vd, o);
        }
        int w = threadIdx.x >> 5;
        if ((threadIdx.x & 31) == 0) { ss[w] = vs; sd[w] = vd; }
        __syncthreads();
        if (valid && (threadIdx.x & 63) == 0) {
            g_asA[node] = ss[w] + ss[w + 1];
            g_adA[node] = sd[w] + sd[w + 1];
        }
    }
}

// ---------------- fused GAT aggregate (+ next-layer transform) ----------------
__device__ __forceinline__ float lrelu(float t) { return t > 0.f ? t : NEG * t; }

__device__ __forceinline__ void acc_row8(float* acc, uint4 raw, float wt) {
    __half2 p0 = *reinterpret_cast<__half2*>(&raw.x);
    __half2 p1 = *reinterpret_cast<__half2*>(&raw.y);
    __half2 p2 = *reinterpret_cast<__half2*>(&raw.z);
    __half2 p3 = *reinterpret_cast<__half2*>(&raw.w);
    float2 f0 = __half22float2(p0);
    float2 f1 = __half22float2(p1);
    float2 f2 = __half22float2(p2);
    float2 f3 = __half22float2(p3);
    acc[0] += wt * f0.x;  acc[1] += wt * f0.y;
    acc[2] += wt * f1.x;  acc[3] += wt * f1.y;
    acc[4] += wt * f2.x;  acc[5] += wt * f2.y;
    acc[6] += wt * f3.x;  acc[7] += wt * f3.y;
}

__global__ __launch_bounds__(256) void k_agg_tr(
    int pp,                              // 0: read A write B; 1: read B write A
    int mode,                            // 0: fused transform; 1: final
    const float* __restrict__ bias,
    const float* __restrict__ Wn,
    const float* __restrict__ asn,
    const float* __restrict__ adn,
    int n, int nblocks)
{
    __shared__ float2 sW[DH * 32];
    __shared__ float sRow[8][DH];
    const __half* hin  = pp ? g_h16B : g_h16A;
    __half*       hout = pp ? g_h16A : g_h16B;
    const float*  as_c = pp ? g_asB : g_asA;
    const float*  ad_c = pp ? g_adB : g_adA;
    float*        as_n = pp ? g_asA : g_asB;
    float*        ad_n = pp ? g_adA : g_adB;

    int tid = threadIdx.x;
    if (mode == 0) {
        for (int i = tid; i < DH * 32; i += 256) sW[i] = ((const float2*)Wn)[i];
        __syncthreads();
    }
    int wid = tid >> 5;
    int lane = tid & 31;
    int grp = lane >> 3;    // edge group 0..3
    int c8 = lane & 7;      // uint4 index within 128B row
    float2 an2 = make_float2(0.f, 0.f), dn2 = make_float2(0.f, 0.f);
    if (mode == 0) {
        an2 = ((const float2*)asn)[lane];
        dn2 = ((const float2*)adn)[lane];
    }
    const uint4* __restrict__ h4 = (const uint4*)hin;
    float4 bb0 = ((const float4*)bias)[c8 * 2];
    float4 bb1 = ((const float4*)bias)[c8 * 2 + 1];

    for (int blk = blockIdx.x; blk < nblocks; blk += gridDim.x) {
        int node = blk * 8 + wid;
        if (node < n) {
            int start = g_ptr[node];
            int end = g_ptr[node + 1];
            int deg = end - start;   // >= 1
            float ad = ad_c[node];
            float acc[8] = {0.f, 0.f, 0.f, 0.f, 0.f, 0.f, 0.f, 0.f};
            float s = 0.f;           // lane-local unnormalized weight sum

            if (deg <= 32) {
                int sv = 0;
                float w = 0.f;
                if (lane < deg) {
                    sv = g_src[start + lane];
                    w = __expf(lrelu(as_c[sv] + ad));   // unnormalized; |e|<<88
                }
                s = w;
                int idx = grp;
                int st = __shfl_sync(0xffffffffu, sv, idx);
                float wt = __shfl_sync(0xffffffffu, w, idx);
                if (idx >= deg) wt = 0.f;
                uint4 raw = h4[(size_t)st * 8 + c8];
                for (int t = 4; t < deg; t += 4) {
                    int idx2 = t + grp;
                    int st2 = __shfl_sync(0xffffffffu, sv, idx2 & 31);
                    float wt2 = __shfl_sync(0xffffffffu, w, idx2 & 31);
                    if (idx2 >= deg) wt2 = 0.f;
                    uint4 raw2 = h4[(size_t)st2 * 8 + c8];
                    acc_row8(acc, raw, wt);
                    raw = raw2;
                    wt = wt2;
                }
                acc_row8(acc, raw, wt);
            } else {
                for (int base = start; base < end; base += 32) {
                    int cnt = min(32, end - base);
                    int sv = 0;
                    float w = 0.f;
                    if (lane < cnt) {
                        sv = g_src[base + lane];
                        w = __expf(lrelu(as_c[sv] + ad));
                    }
                    s += w;
                    int idx = grp;
                    int st = __shfl_sync(0xffffffffu, sv, idx);
                    float wt = __shfl_sync(0xffffffffu, w, idx);
                    if (idx >= cnt) wt = 0.f;
                    uint4 raw = h4[(size_t)st * 8 + c8];
                    for (int t = 4; t < cnt; t += 4) {
                        int idx2 = t + grp;
                        int st2 = __shfl_sync(0xffffffffu, sv, idx2 & 31);
                        float wt2 = __shfl_sync(0xffffffffu, w, idx2 & 31);
                        if (idx2 >= cnt) wt2 = 0.f;
                        uint4 raw2 = h4[(size_t)st2 * 8 + c8];
                        acc_row8(acc, raw, wt);
                        raw = raw2;
                        wt = wt2;
                    }
                    acc_row8(acc, raw, wt);
                }
            }
#pragma unroll
            for (int o = 16; o > 0; o >>= 1) s += __shfl_xor_sync(0xffffffffu, s, o);
#pragma unroll
            for (int i = 0; i < 8; i++) {
                acc[i] += __shfl_xor_sync(0xffffffffu, acc[i], 8);
                acc[i] += __shfl_xor_sync(0xffffffffu, acc[i], 16);
            }
            float invs = 1.f / (s + 1e-16f);
            acc[0] = acc[0] * invs + bb0.x;
            acc[1] = acc[1] * invs + bb0.y;
            acc[2] = acc[2] * invs + bb0.z;
            acc[3] = acc[3] * invs + bb0.w;
            acc[4] = acc[4] * invs + bb1.x;
            acc[5] = acc[5] * invs + bb1.y;
            acc[6] = acc[6] * invs + bb1.z;
            acc[7] = acc[7] * invs + bb1.w;

            if (mode == 1) {
                if (grp == 0) {
                    ((float4*)g_hA)[(size_t)node * 16 + c8 * 2] =
                        make_float4(acc[0], acc[1], acc[2], acc[3]);
                    ((float4*)g_hA)[(size_t)node * 16 + c8 * 2 + 1] =
                        make_float4(acc[4], acc[5], acc[6], acc[7]);
                }
            } else {
                if (grp == 0) {
                    float4* sr = (float4*)&sRow[wid][c8 * 8];
                    sr[0] = make_float4(acc[0], acc[1], acc[2], acc[3]);
                    sr[1] = make_float4(acc[4], acc[5], acc[6], acc[7]);
                }
                __syncwarp();
                float o0 = 0.f, o1 = 0.f;
#pragma unroll
                for (int k = 0; k < DH; k++) {
                    float r = sRow[wid][k];
                    float2 w2 = sW[k * 32 + lane];
                    o0 += r * w2.x;
                    o1 += r * w2.y;
                }
                __syncwarp();
                ((__half2*)hout)[(size_t)node * 32 + lane] = __floats2half2_rn(o0, o1);
                float vs = o0 * an2.x + o1 * an2.y;
                float vd = o0 * dn2.x + o1 * dn2.y;
#pragma unroll
                for (int o = 16; o > 0; o >>= 1) {
                    vs += __shfl_xor_sync(0xffffffffu, vs, o);
                    vd += __shfl_xor_sync(0xffffffffu, vd, o);
                }
                if (lane == 0) {
                    as_n[node] = vs;
                    ad_n[node] = vd;
                }
            }
        }
    }
}

// ---------------- pooling (sorted batch, run-length pre-aggregation) ----------------
__global__ void k_pool(int n) {
    int c = threadIdx.x & 63;
    int chunk = blockIdx.x * 4 + (threadIdx.x >> 6);
    int i0 = chunk * 64;
    if (i0 >= n) return;
    int iend = min(i0 + 64, n);
    float acc = 0.f;
    int cacc = 0;
    int cur = g_batch[i0];
    for (int i = i0; i < iend; i++) {
        int b = g_batch[i];
        if (b != cur) {
            atomicAdd(&g_pool[cur * DH + c], acc);
            if (c == 0) atomicAdd(&g_cnt[cur], cacc);
            acc = 0.f; cacc = 0; cur = b;
        }
        acc += g_hA[(size_t)i * DH + c];
        cacc++;
    }
    atomicAdd(&g_pool[cur * DH + c], acc);
    if (c == 0) atomicAdd(&g_cnt[cur], cacc);
}

// ---------------- classifier head ----------------
__global__ void k_final(const float* __restrict__ Wl, const float* __restrict__ bl,
                        float* __restrict__ out) {
    int t = blockIdx.x * blockDim.x + threadIdx.x;
    if (t >= NG * NC) return;
    int g = t / NC;
    int cls = t % NC;
    float invc = 1.f / fmaxf((float)g_cnt[g], 1.f);
    float dot = 0.f;
#pragma unroll
    for (int d = 0; d < DH; d++) dot += g_pool[g * DH + d] * Wl[d * NC + cls];
    out[t] = dot * invc + bl[cls];
}

// ---------------- host launcher ----------------
extern "C" void kernel_launch(void* const* d_in, const int* in_sizes, int n_in,
                              void* d_out, int out_size) {
    const float* x = (const float*)d_in[0];
    const float* pos = (const float*)d_in[1];
    const void* ei = d_in[2];
    const void* batch = d_in[3];
    const float* W1 = (const float*)d_in[4];
    const float* as1 = (const float*)d_in[5];
    const float* ad1 = (const float*)d_in[6];
    const float* b1 = (const float*)d_in[7];
    const float* W2 = (const float*)d_in[8];
    const float* as2 = (const float*)d_in[9];
    const float* ad2 = (const float*)d_in[10];
    const float* b2 = (const float*)d_in[11];
    const float* W3 = (const float*)d_in[12];
    const float* as3 = (const float*)d_in[13];
    const float* ad3 = (const float*)d_in[14];
    const float* b3 = (const float*)d_in[15];
    const float* Wl = (const float*)d_in[16];
    const float* bl = (const float*)d_in[17];
    float* out = (float*)d_out;

    int n = in_sizes[0];
    int E = in_sizes[2] / 2;
    int nb = (n + 2047) / 2048;   // <= 49 blocks, all resident
    int nblocks = (n + 7) / 8;

    int prepT = E > n ? E : n;
    k_prep<<<(prepT + 255) / 256, 256>>>(ei, batch, E, n);      // launch 1
    k_scan<<<nb, 256>>>(n);                                     // launch 2

    int sb = (E + n + 255) / 256;
    int tb = (n + 3) / 4;
    k_scatter_tr<<<sb + tb, 256>>>(E, n, sb, x, pos, W1, as1, ad1);  // launch 3

    int tg = 1184;   // persistent blocks (8/SM)
    k_agg_tr<<<tg, 256>>>(0, 0, b1, W2, as2, ad2, n, nblocks);       // launch 4 (profiled)
    k_agg_tr<<<tg, 256>>>(1, 0, b2, W3, as3, ad3, n, nblocks);
    k_agg_tr<<<nblocks, 256>>>(0, 1, b3, W3, as3, ad3, n, nblocks);

    int chunks = (n + 63) / 64;
    k_pool<<<(chunks + 3) / 4, 256>>>(n);
    k_final<<<(NG * NC + 255) / 256, 256>>>(Wl, bl, out);
}